// round 15
// baseline (speedup 1.0000x reference)
#include <cuda_runtime.h>
#include <math.h>
#include <stdint.h>

#define NN 128
#define DD 2048
#define EPSF 1e-12f
#define MARGINF 0.3f
#define KCHUNK 64        // K per GEMM block
#define KP 32            // k-pairs per chunk
#define NKCH 32          // K chunks (32*64 = 2048)
#define NBLK 128         // one block per SM, all co-resident
#define S2 66            // smem row stride in float2

// ---------------- device scratch (no allocations allowed) ----------------
// g_part now holds per-chunk SQUARED-DISTANCE partials:
//   part[i][kc][j] = ||f1_i||^2_kc + ||f2_j||^2_kc - 2*dot_kc  ( = sum (a-b)^2 )
__device__ float g_part[NN * NKCH * NN];   // 2 MB
__device__ float g_ap[NN];                 // hardest-positive distance per row
__device__ float g_dan[NN];                // dist_an per anchor
__device__ unsigned g_cl, g_ch, g_c2;      // half barriers + finalize counter

__device__ __forceinline__ void ffma2(unsigned long long& acc,
                                      unsigned long long a, unsigned long long b) {
    asm("fma.rn.f32x2 %0, %1, %2, %0;" : "+l"(acc) : "l"(a), "l"(b));
}
__device__ __forceinline__ float2 up2(unsigned long long v) {
    float2 r;
    asm("mov.b64 {%0, %1}, %2;" : "=f"(r.x), "=f"(r.y) : "l"(v));
    return r;
}

__global__ void __launch_bounds__(256, 1)
k_fused(const float* __restrict__ f1, const float* __restrict__ f2,
        const int* __restrict__ tgt, float* __restrict__ out, int out_size) {
    const int tid = threadIdx.x;
    const int bid = blockIdx.x;
    const int w = tid >> 5, lane = tid & 31;

    __shared__ float2 As2[KP][S2];   // As2[kp][row] = (A[2kp],A[2kp+1]) of row
    __shared__ float2 Bs2[KP][S2];
    __shared__ unsigned s_bal[4];
    __shared__ float  s_nrm[NN];     // [0,64): A-row chunk norms, [64,128): B
    __shared__ float  s_dot[NN];
    __shared__ float  s_ap[4];
    __shared__ unsigned long long s_k1[4], s_k2[4];
    __shared__ float  red[8][2];

    // ================= Phase A: split-K d2-GEMM ============================
    const int quad = bid >> 5;            // 0..3
    const int kc = bid & 31;
    const int i0 = (quad & 1) * 64;
    const int j0 = (quad >> 1) * 64;
    const int k0 = kc * KCHUNK;

    // GEMM tile loads: 64 rows x 64 K per matrix = 1024 float4; 4 per thread
    float4 va[4], vb[4];
    int rw[4], k4[4];
    #pragma unroll
    for (int s = 0; s < 4; s++) {
        const int idx = tid + 256 * s;    // 0..1023
        rw[s] = idx >> 4;                 // 0..63
        k4[s] = idx & 15;
        va[s] = *(const float4*)(f1 + (size_t)(i0 + rw[s]) * DD + k0 + k4[s] * 4);
        vb[s] = *(const float4*)(f2 + (size_t)(j0 + rw[s]) * DD + k0 + k4[s] * 4);
    }
    // targets via direct LDG (rides the same MLP window)
    const int ti = __ldg(&tgt[bid]);
    const int tj = (tid < NN) ? __ldg(&tgt[tid]) : ti;

    // ---- register/STS work ordered before ONE sync ----
    const bool pos = (tid < NN) && (tj == ti);
    unsigned mybal = 0;
    if (tid < NN) {
        mybal = __ballot_sync(0xffffffffu, !pos);
        if (lane == 0) s_bal[w] = mybal;
    }

    // stage GEMM tiles, k-pair interleaved
    #pragma unroll
    for (int s = 0; s < 4; s++) {
        As2[2 * k4[s] + 0][rw[s]] = make_float2(va[s].x, va[s].y);
        As2[2 * k4[s] + 1][rw[s]] = make_float2(va[s].z, va[s].w);
        Bs2[2 * k4[s] + 0][rw[s]] = make_float2(vb[s].x, vb[s].y);
        Bs2[2 * k4[s] + 1][rw[s]] = make_float2(vb[s].z, vb[s].w);
    }

    __syncthreads();   // tiles + s_bal visible

    // rank of column tid among negatives (ascending column order)
    int rank = 0;
    if (tid < NN) {
        #pragma unroll
        for (int q = 0; q < 4; q++) rank += (q < w) ? __popc(s_bal[q]) : 0;
        rank += __popc(mybal & ((1u << lane) - 1u));
    }

    // 4x4 register tile; warp footprint = 4 (A) x 8 (B) distinct addresses
    const int ty4 = ((w >> 1) * 4 + (lane >> 3)) * 4;   // 16 row-groups
    const int tx4 = ((w & 1) * 8 + (lane & 7)) * 4;     // 16 col-groups

    unsigned long long acc[4][4];
    #pragma unroll
    for (int m = 0; m < 4; m++)
        #pragma unroll
        for (int n = 0; n < 4; n++) acc[m][n] = 0ull;

    #pragma unroll
    for (int kp = 0; kp < KP; kp++) {
        ulonglong2 a0 = *(const ulonglong2*)&As2[kp][ty4];
        ulonglong2 a1 = *(const ulonglong2*)&As2[kp][ty4 + 2];
        ulonglong2 b0 = *(const ulonglong2*)&Bs2[kp][tx4];
        ulonglong2 b1 = *(const ulonglong2*)&Bs2[kp][tx4 + 2];
        unsigned long long A[4] = {a0.x, a0.y, a1.x, a1.y};
        unsigned long long B[4] = {b0.x, b0.y, b1.x, b1.y};
        #pragma unroll
        for (int m = 0; m < 4; m++)
            #pragma unroll
            for (int n = 0; n < 4; n++)
                ffma2(acc[m][n], A[m], B[n]);
    }

    // chunk norms from the resident smem tiles (threads 0-127; conflict-free:
    // 32 consecutive lanes read 32 consecutive 8B rows = 256B contiguous)
    if (tid < 128) {
        const int row = tid & 63;
        const float2* src = (tid < 64) ? &As2[0][row] : &Bs2[0][row];
        float q0 = 0.f, q1 = 0.f, q2 = 0.f, q3 = 0.f;
        #pragma unroll
        for (int kp = 0; kp < KP; kp += 4) {
            float2 v0 = src[(size_t)(kp + 0) * S2];
            float2 v1 = src[(size_t)(kp + 1) * S2];
            float2 v2 = src[(size_t)(kp + 2) * S2];
            float2 v3 = src[(size_t)(kp + 3) * S2];
            q0 += v0.x * v0.x + v0.y * v0.y;
            q1 += v1.x * v1.x + v1.y * v1.y;
            q2 += v2.x * v2.x + v2.y * v2.y;
            q3 += v3.x * v3.x + v3.y * v3.y;
        }
        s_nrm[tid] = (q0 + q1) + (q2 + q3);
    }
    __syncthreads();   // s_nrm visible

    // epilogue: write per-chunk SQUARED-DISTANCE partials
    {
        float nA[4], nB[4];
        #pragma unroll
        for (int m = 0; m < 4; m++) nA[m] = s_nrm[ty4 + m];
        #pragma unroll
        for (int n = 0; n < 4; n++) nB[n] = s_nrm[64 + tx4 + n];
        #pragma unroll
        for (int m = 0; m < 4; m++) {
            float v[4];
            #pragma unroll
            for (int n = 0; n < 4; n++) {
                float2 p = up2(acc[m][n]);
                v[n] = nA[m] + nB[n] - 2.f * (p.x + p.y);
            }
            *(float4*)&g_part[((size_t)(i0 + ty4 + m) * NKCH + kc) * NN + j0 + tx4] =
                make_float4(v[0], v[1], v[2], v[3]);
        }
    }

    // preload the anchor row for phase C: depends only on bid, so its load
    // latency is absorbed by the barrier spin below.
    const int kanc = (bid < 32) ? bid : (bid < 64) ? (bid + 32)
                   : (bid < 96) ? (bid - 32) : bid;
    const float4* xk = (const float4*)(f1 + (size_t)kanc * DD);
    const float4 vk0 = xk[tid];
    const float4 vk1 = xk[tid + 256];

    // ---- HALF grid barrier: arrive at own i-half counter, wait only for the
    // 64 producer blocks of this block's consumer row (bid). arrive-then-wait
    // on independent counters: no deadlock. release/acquire ordering as before.
    __syncthreads();
    if (tid == 0) {
        unsigned* mine = (quad & 1) ? &g_ch : &g_cl;   // produces rows i0=64/0
        asm volatile("red.release.gpu.global.add.u32 [%0], 1;"
                     :: "l"(mine) : "memory");
        unsigned* need = (bid < 64) ? &g_cl : &g_ch;   // consumes row bid
        unsigned v;
        do {
            asm volatile("ld.acquire.gpu.global.u32 %0, [%1];"
                         : "=r"(v) : "l"(need) : "memory");
        } while (v != 64u);
    }
    __syncthreads();

    // ================= Phase B: distances + hard-example selection ========
    // 2-way split over all 256 threads: thread {j, j+128} each sum 16 chunks.
    {
        const int i = bid;
        const int j = tid & 127;
        const int kh = tid >> 7;           // 0: chunks 0-15, 1: chunks 16-31

        const float* pp = g_part + ((size_t)i * NKCH + kh * 16) * NN + j;
        float a0 = 0.f, a1 = 0.f, a2 = 0.f, a3 = 0.f;
        #pragma unroll
        for (int c = 0; c < 16; c += 4) {
            a0 += __ldcg(pp + (size_t)(c + 0) * NN);
            a1 += __ldcg(pp + (size_t)(c + 1) * NN);
            a2 += __ldcg(pp + (size_t)(c + 2) * NN);
            a3 += __ldcg(pp + (size_t)(c + 3) * NN);
        }
        float half_d2 = (a0 + a1) + (a2 + a3);
        if (tid >= NN) s_dot[j] = half_d2;
        __syncthreads();

        if (tid < NN) {
            float d2 = half_d2 + s_dot[j];    // full squared distance
            float d = sqrtf(fmaxf(d2, EPSF));

            float apv = pos ? d : -INFINITY;
            // (distance, column) lexicographic key: min == argmin with
            // first-occurrence tie-break (d > 0, float bits order-preserving)
            unsigned long long key =
                ((unsigned long long)__float_as_uint(d) << 32) | (unsigned)j;
            unsigned long long k1 = (!pos && rank < 56) ? key : ~0ull;
            unsigned long long k2 = (!pos && rank >= 56 && rank < 112) ? key : ~0ull;

            #pragma unroll
            for (int o = 16; o; o >>= 1) {
                apv = fmaxf(apv, __shfl_xor_sync(0xffffffffu, apv, o));
                unsigned long long t1 = __shfl_xor_sync(0xffffffffu, k1, o);
                unsigned long long t2 = __shfl_xor_sync(0xffffffffu, k2, o);
                k1 = (t1 < k1) ? t1 : k1;
                k2 = (t2 < k2) ? t2 : k2;
            }
            if (lane == 0) { s_ap[w] = apv; s_k1[w] = k1; s_k2[w] = k2; }
        }
        __syncthreads();
    }

    // every thread combines the 4 warp keys locally (no serial tid0 step)
    int sela, selb;
    {
        unsigned long long m1 = s_k1[0], m2 = s_k2[0];
        #pragma unroll
        for (int q = 1; q < 4; q++) {
            if (s_k1[q] < m1) m1 = s_k1[q];
            if (s_k2[q] < m2) m2 = s_k2[q];
        }
        sela = (int)(m1 & 0xffffffffull);
        selb = (int)(m2 & 0xffffffffull);
        if (tid == 0)
            g_ap[bid] = fmaxf(fmaxf(s_ap[0], s_ap[1]), fmaxf(s_ap[2], s_ap[3]));
    }

    // ========== Phase C (no barrier): dist_an for anchor kanc ==============
    {
        const float4* xa = (const float4*)(f1 + (size_t)sela * DD);
        const float4* xb = (const float4*)(f1 + (size_t)selb * DD);

        float4 a0 = xa[tid],       b0v = xb[tid];
        float4 a1 = xa[tid + 256], b1v = xb[tid + 256];

        float4 fm0, fm1;
        fm0.x = 0.5f * (a0.x + b0v.x); fm0.y = 0.5f * (a0.y + b0v.y);
        fm0.z = 0.5f * (a0.z + b0v.z); fm0.w = 0.5f * (a0.w + b0v.w);
        fm1.x = 0.5f * (a1.x + b1v.x); fm1.y = 0.5f * (a1.y + b1v.y);
        fm1.z = 0.5f * (a1.z + b1v.z); fm1.w = 0.5f * (a1.w + b1v.w);

        float s1 = vk0.x * vk0.x + vk0.y * vk0.y + vk0.z * vk0.z + vk0.w * vk0.w
                 + fm0.x * fm0.x + fm0.y * fm0.y + fm0.z * fm0.z + fm0.w * fm0.w
                 + vk1.x * vk1.x + vk1.y * vk1.y + vk1.z * vk1.z + vk1.w * vk1.w
                 + fm1.x * fm1.x + fm1.y * fm1.y + fm1.z * fm1.z + fm1.w * fm1.w;
        float ab = vk0.x * fm0.x + vk0.y * fm0.y + vk0.z * fm0.z + vk0.w * fm0.w
                 + vk1.x * fm1.x + vk1.y * fm1.y + vk1.z * fm1.z + vk1.w * fm1.w;

        #pragma unroll
        for (int o = 16; o; o >>= 1) {
            s1 += __shfl_xor_sync(0xffffffffu, s1, o);
            ab += __shfl_xor_sync(0xffffffffu, ab, o);
        }
        if (lane == 0) { red[w][0] = s1; red[w][1] = ab; }
        __syncthreads();
    }

    // ================= finalize: last-arriving block (parallel) ============
    int last = 0;
    if (tid == 0) {
        float t1 = 0.f, t2 = 0.f;
        #pragma unroll
        for (int q = 0; q < 8; q++) { t1 += red[q][0]; t2 += red[q][1]; }
        float d2 = t1 - 2.f * t2;
        g_dan[kanc] = sqrtf(fmaxf(d2, EPSF));
        unsigned done;
        asm volatile("atom.acq_rel.gpu.global.add.u32 %0, [%1], 1;"
                     : "=r"(done) : "l"(&g_c2) : "memory");
        last = (done == NBLK - 1) ? 1 : 0;
    }
    if (__syncthreads_or(last)) {
        float t = 0.f;
        if (tid < NN)
            t = __ldcg(&g_ap[tid]) - __ldcg(&g_dan[tid]) + MARGINF;
        float v = (tid < NN && t > 0.f) ? t : 0.f;
        float c = (tid < NN && t > 0.f) ? 1.f : 0.f;
        #pragma unroll
        for (int o = 16; o; o >>= 1) {
            v += __shfl_xor_sync(0xffffffffu, v, o);
            c += __shfl_xor_sync(0xffffffffu, c, o);
        }
        if (lane == 0) { red[w][0] = v; red[w][1] = c; }
        __syncthreads();
        if (tid == 0) {
            float s = 0.f, cc = 0.f;
            #pragma unroll
            for (int q = 0; q < 4; q++) { s += red[q][0]; cc += red[q][1]; }
            out[0] = s * (1.0f / 128.0f);
            if (out_size > 1) out[1] = cc;
            // reset barriers for next graph replay
            g_cl = 0u; g_ch = 0u; g_c2 = 0u;
        }
    }
}

// ---------------- launch ----------------
extern "C" void kernel_launch(void* const* d_in, const int* in_sizes, int n_in,
                              void* d_out, int out_size) {
    const float* f1 = (const float*)d_in[0];
    const float* f2 = (const float*)d_in[1];
    const int*   tgt = (const int*)d_in[2];
    (void)in_sizes; (void)n_in;

    k_fused<<<NBLK, 256>>>(f1, f2, tgt, (float*)d_out, out_size);
}

// round 16
// speedup vs baseline: 1.0226x; 1.0226x over previous
#include <cuda_runtime.h>
#include <math.h>
#include <stdint.h>

#define NN 128
#define DD 2048
#define EPSF 1e-12f
#define MARGINF 0.3f
#define KCHUNK 64        // K per GEMM block
#define KP 32            // k-pairs per chunk
#define NKCH 32          // K chunks (32*64 = 2048)
#define NBLK 128         // one block per SM, all co-resident
#define S2 66            // smem row stride in float2

// ---------------- device scratch (no allocations allowed) ----------------
// per-chunk SQUARED-DISTANCE partials:
//   part[i][kc][j] = ||f1_i||^2_kc + ||f2_j||^2_kc - 2*dot_kc ( = sum (a-b)^2 )
__device__ float g_part[NN * NKCH * NN];   // 2 MB
__device__ float g_ap[NN];                 // hardest-positive distance per row
__device__ float g_dan[NN];                // dist_an per anchor
__device__ unsigned g_cl, g_ch, g_c2;      // half barriers + finalize counter

__device__ __forceinline__ void ffma2(unsigned long long& acc,
                                      unsigned long long a, unsigned long long b) {
    asm("fma.rn.f32x2 %0, %1, %2, %0;" : "+l"(acc) : "l"(a), "l"(b));
}
__device__ __forceinline__ float2 up2(unsigned long long v) {
    float2 r;
    asm("mov.b64 {%0, %1}, %2;" : "=f"(r.x), "=f"(r.y) : "l"(v));
    return r;
}

__global__ void __launch_bounds__(256, 1)
k_fused(const float* __restrict__ f1, const float* __restrict__ f2,
        const int* __restrict__ tgt, float* __restrict__ out, int out_size) {
    const int tid = threadIdx.x;
    const int bid = blockIdx.x;
    const int w = tid >> 5, lane = tid & 31;

    __shared__ float2 As2[KP][S2];   // As2[kp][row] = (A[2kp],A[2kp+1]) of row
    __shared__ float2 Bs2[KP][S2];
    __shared__ unsigned s_bal[4];
    __shared__ float  s_nrm[NN];     // [0,64): A-row chunk norms, [64,128): B
    __shared__ float  s_dot[NN];
    __shared__ float  s_ap[4];
    __shared__ unsigned long long s_k1[4], s_k2[4];
    __shared__ float  red[8][2];

    // ================= Phase A: split-K d2-GEMM ============================
    const int quad = bid >> 5;            // 0..3
    const int kc = bid & 31;
    const int i0 = (quad & 1) * 64;
    const int j0 = (quad >> 1) * 64;
    const int k0 = kc * KCHUNK;

    // GEMM tile loads: 64 rows x 64 K per matrix = 1024 float4; 4 per thread
    float4 va[4], vb[4];
    int rw[4], k4[4];
    #pragma unroll
    for (int s = 0; s < 4; s++) {
        const int idx = tid + 256 * s;    // 0..1023
        rw[s] = idx >> 4;                 // 0..63
        k4[s] = idx & 15;
        va[s] = *(const float4*)(f1 + (size_t)(i0 + rw[s]) * DD + k0 + k4[s] * 4);
        vb[s] = *(const float4*)(f2 + (size_t)(j0 + rw[s]) * DD + k0 + k4[s] * 4);
    }
    // targets via direct LDG (rides the same MLP window)
    const int ti = __ldg(&tgt[bid]);
    const int tj = (tid < NN) ? __ldg(&tgt[tid]) : ti;

    // ---- register/STS work ordered before ONE sync ----
    const bool pos = (tid < NN) && (tj == ti);
    unsigned mybal = 0;
    if (tid < NN) {
        mybal = __ballot_sync(0xffffffffu, !pos);
        if (lane == 0) s_bal[w] = mybal;
    }

    // stage GEMM tiles, k-pair interleaved
    #pragma unroll
    for (int s = 0; s < 4; s++) {
        As2[2 * k4[s] + 0][rw[s]] = make_float2(va[s].x, va[s].y);
        As2[2 * k4[s] + 1][rw[s]] = make_float2(va[s].z, va[s].w);
        Bs2[2 * k4[s] + 0][rw[s]] = make_float2(vb[s].x, vb[s].y);
        Bs2[2 * k4[s] + 1][rw[s]] = make_float2(vb[s].z, vb[s].w);
    }

    __syncthreads();   // tiles + s_bal visible

    // chunk norms BEFORE the kp loop: acc not yet live, va/vb dead -> no
    // register-pressure collision (R15's 254-reg mistake). threads 0-127,
    // conflict-free (32 consecutive lanes read 256B contiguous smem).
    if (tid < 128) {
        const int row = tid & 63;
        const float2* src = (tid < 64) ? &As2[0][row] : &Bs2[0][row];
        float q0 = 0.f, q1 = 0.f, q2 = 0.f, q3 = 0.f;
        #pragma unroll
        for (int kp = 0; kp < KP; kp += 4) {
            float2 v0 = src[(size_t)(kp + 0) * S2];
            float2 v1 = src[(size_t)(kp + 1) * S2];
            float2 v2 = src[(size_t)(kp + 2) * S2];
            float2 v3 = src[(size_t)(kp + 3) * S2];
            q0 += v0.x * v0.x + v0.y * v0.y;
            q1 += v1.x * v1.x + v1.y * v1.y;
            q2 += v2.x * v2.x + v2.y * v2.y;
            q3 += v3.x * v3.x + v3.y * v3.y;
        }
        s_nrm[tid] = (q0 + q1) + (q2 + q3);
    }

    // rank of column tid among negatives (ascending column order)
    int rank = 0;
    if (tid < NN) {
        #pragma unroll
        for (int q = 0; q < 4; q++) rank += (q < w) ? __popc(s_bal[q]) : 0;
        rank += __popc(mybal & ((1u << lane) - 1u));
    }

    __syncthreads();   // s_nrm visible (tiles unchanged)

    // 4x4 register tile; warp footprint = 4 (A) x 8 (B) distinct addresses
    const int ty4 = ((w >> 1) * 4 + (lane >> 3)) * 4;   // 16 row-groups
    const int tx4 = ((w & 1) * 8 + (lane & 7)) * 4;     // 16 col-groups

    unsigned long long acc[4][4];
    #pragma unroll
    for (int m = 0; m < 4; m++)
        #pragma unroll
        for (int n = 0; n < 4; n++) acc[m][n] = 0ull;

    #pragma unroll
    for (int kp = 0; kp < KP; kp++) {
        ulonglong2 a0 = *(const ulonglong2*)&As2[kp][ty4];
        ulonglong2 a1 = *(const ulonglong2*)&As2[kp][ty4 + 2];
        ulonglong2 b0 = *(const ulonglong2*)&Bs2[kp][tx4];
        ulonglong2 b1 = *(const ulonglong2*)&Bs2[kp][tx4 + 2];
        unsigned long long A[4] = {a0.x, a0.y, a1.x, a1.y};
        unsigned long long B[4] = {b0.x, b0.y, b1.x, b1.y};
        #pragma unroll
        for (int m = 0; m < 4; m++)
            #pragma unroll
            for (int n = 0; n < 4; n++)
                ffma2(acc[m][n], A[m], B[n]);
    }

    // epilogue: write per-chunk SQUARED-DISTANCE partials
    {
        #pragma unroll
        for (int m = 0; m < 4; m++) {
            const float nA = s_nrm[ty4 + m];
            float v[4];
            #pragma unroll
            for (int n = 0; n < 4; n++) {
                float2 p = up2(acc[m][n]);
                v[n] = nA + s_nrm[64 + tx4 + n] - 2.f * (p.x + p.y);
            }
            *(float4*)&g_part[((size_t)(i0 + ty4 + m) * NKCH + kc) * NN + j0 + tx4] =
                make_float4(v[0], v[1], v[2], v[3]);
        }
    }

    // preload the anchor row for phase C: depends only on bid, so its load
    // latency is absorbed by the barrier spin below.
    const int kanc = (bid < 32) ? bid : (bid < 64) ? (bid + 32)
                   : (bid < 96) ? (bid - 32) : bid;
    const float4* xk = (const float4*)(f1 + (size_t)kanc * DD);
    const float4 vk0 = xk[tid];
    const float4 vk1 = xk[tid + 256];

    // ---- HALF grid barrier: arrive at own i-half counter (release), wait
    // only for the 64 producers of this block's consumer row (acquire).
    // arrive-then-wait on independent counters: deadlock-free.
    __syncthreads();
    if (tid == 0) {
        unsigned* mine = (quad & 1) ? &g_ch : &g_cl;   // produces rows i0=64/0
        asm volatile("red.release.gpu.global.add.u32 [%0], 1;"
                     :: "l"(mine) : "memory");
        unsigned* need = (bid < 64) ? &g_cl : &g_ch;   // consumes row bid
        unsigned v;
        do {
            asm volatile("ld.acquire.gpu.global.u32 %0, [%1];"
                         : "=r"(v) : "l"(need) : "memory");
        } while (v != 64u);
    }
    __syncthreads();

    // ================= Phase B: distances + hard-example selection ========
    // 2-way split over all 256 threads: thread {j, j+128} each sum 16 chunks.
    {
        const int i = bid;
        const int j = tid & 127;
        const int kh = tid >> 7;           // 0: chunks 0-15, 1: chunks 16-31

        const float* pp = g_part + ((size_t)i * NKCH + kh * 16) * NN + j;
        float a0 = 0.f, a1 = 0.f, a2 = 0.f, a3 = 0.f;
        #pragma unroll
        for (int c = 0; c < 16; c += 4) {
            a0 += __ldcg(pp + (size_t)(c + 0) * NN);
            a1 += __ldcg(pp + (size_t)(c + 1) * NN);
            a2 += __ldcg(pp + (size_t)(c + 2) * NN);
            a3 += __ldcg(pp + (size_t)(c + 3) * NN);
        }
        float half_d2 = (a0 + a1) + (a2 + a3);
        if (tid >= NN) s_dot[j] = half_d2;
        __syncthreads();

        if (tid < NN) {
            float d2 = half_d2 + s_dot[j];    // full squared distance
            float d = sqrtf(fmaxf(d2, EPSF));

            float apv = pos ? d : -INFINITY;
            // (distance, column) lexicographic key: min == argmin with
            // first-occurrence tie-break (d > 0, float bits order-preserving)
            unsigned long long key =
                ((unsigned long long)__float_as_uint(d) << 32) | (unsigned)j;
            unsigned long long k1 = (!pos && rank < 56) ? key : ~0ull;
            unsigned long long k2 = (!pos && rank >= 56 && rank < 112) ? key : ~0ull;

            #pragma unroll
            for (int o = 16; o; o >>= 1) {
                apv = fmaxf(apv, __shfl_xor_sync(0xffffffffu, apv, o));
                unsigned long long t1 = __shfl_xor_sync(0xffffffffu, k1, o);
                unsigned long long t2 = __shfl_xor_sync(0xffffffffu, k2, o);
                k1 = (t1 < k1) ? t1 : k1;
                k2 = (t2 < k2) ? t2 : k2;
            }
            if (lane == 0) { s_ap[w] = apv; s_k1[w] = k1; s_k2[w] = k2; }
        }
        __syncthreads();
    }

    // every thread combines the 4 warp keys locally (no serial tid0 step)
    int sela, selb;
    {
        unsigned long long m1 = s_k1[0], m2 = s_k2[0];
        #pragma unroll
        for (int q = 1; q < 4; q++) {
            if (s_k1[q] < m1) m1 = s_k1[q];
            if (s_k2[q] < m2) m2 = s_k2[q];
        }
        sela = (int)(m1 & 0xffffffffull);
        selb = (int)(m2 & 0xffffffffull);
        if (tid == 0)
            g_ap[bid] = fmaxf(fmaxf(s_ap[0], s_ap[1]), fmaxf(s_ap[2], s_ap[3]));
    }

    // ========== Phase C (no barrier): dist_an for anchor kanc ==============
    {
        const float4* xa = (const float4*)(f1 + (size_t)sela * DD);
        const float4* xb = (const float4*)(f1 + (size_t)selb * DD);

        float4 a0 = xa[tid],       b0v = xb[tid];
        float4 a1 = xa[tid + 256], b1v = xb[tid + 256];

        float4 fm0, fm1;
        fm0.x = 0.5f * (a0.x + b0v.x); fm0.y = 0.5f * (a0.y + b0v.y);
        fm0.z = 0.5f * (a0.z + b0v.z); fm0.w = 0.5f * (a0.w + b0v.w);
        fm1.x = 0.5f * (a1.x + b1v.x); fm1.y = 0.5f * (a1.y + b1v.y);
        fm1.z = 0.5f * (a1.z + b1v.z); fm1.w = 0.5f * (a1.w + b1v.w);

        float s1 = vk0.x * vk0.x + vk0.y * vk0.y + vk0.z * vk0.z + vk0.w * vk0.w
                 + fm0.x * fm0.x + fm0.y * fm0.y + fm0.z * fm0.z + fm0.w * fm0.w
                 + vk1.x * vk1.x + vk1.y * vk1.y + vk1.z * vk1.z + vk1.w * vk1.w
                 + fm1.x * fm1.x + fm1.y * fm1.y + fm1.z * fm1.z + fm1.w * fm1.w;
        float ab = vk0.x * fm0.x + vk0.y * fm0.y + vk0.z * fm0.z + vk0.w * fm0.w
                 + vk1.x * fm1.x + vk1.y * fm1.y + vk1.z * fm1.z + vk1.w * fm1.w;

        #pragma unroll
        for (int o = 16; o; o >>= 1) {
            s1 += __shfl_xor_sync(0xffffffffu, s1, o);
            ab += __shfl_xor_sync(0xffffffffu, ab, o);
        }
        if (lane == 0) { red[w][0] = s1; red[w][1] = ab; }
        __syncthreads();
    }

    // ================= finalize: last-arriving block (parallel) ============
    int last = 0;
    if (tid == 0) {
        float t1 = 0.f, t2 = 0.f;
        #pragma unroll
        for (int q = 0; q < 8; q++) { t1 += red[q][0]; t2 += red[q][1]; }
        float d2 = t1 - 2.f * t2;
        g_dan[kanc] = sqrtf(fmaxf(d2, EPSF));
        unsigned done;
        asm volatile("atom.acq_rel.gpu.global.add.u32 %0, [%1], 1;"
                     : "=r"(done) : "l"(&g_c2) : "memory");
        last = (done == NBLK - 1) ? 1 : 0;
    }
    if (__syncthreads_or(last)) {
        float t = 0.f;
        if (tid < NN)
            t = __ldcg(&g_ap[tid]) - __ldcg(&g_dan[tid]) + MARGINF;
        float v = (tid < NN && t > 0.f) ? t : 0.f;
        float c = (tid < NN && t > 0.f) ? 1.f : 0.f;
        #pragma unroll
        for (int o = 16; o; o >>= 1) {
            v += __shfl_xor_sync(0xffffffffu, v, o);
            c += __shfl_xor_sync(0xffffffffu, c, o);
        }
        if (lane == 0) { red[w][0] = v; red[w][1] = c; }
        __syncthreads();
        if (tid == 0) {
            float s = 0.f, cc = 0.f;
            #pragma unroll
            for (int q = 0; q < 4; q++) { s += red[q][0]; cc += red[q][1]; }
            out[0] = s * (1.0f / 128.0f);
            if (out_size > 1) out[1] = cc;
            // reset barriers for next graph replay
            g_cl = 0u; g_ch = 0u; g_c2 = 0u;
        }
    }
}

// ---------------- launch ----------------
extern "C" void kernel_launch(void* const* d_in, const int* in_sizes, int n_in,
                              void* d_out, int out_size) {
    const float* f1 = (const float*)d_in[0];
    const float* f2 = (const float*)d_in[1];
    const int*   tgt = (const int*)d_in[2];
    (void)in_sizes; (void)n_in;

    k_fused<<<NBLK, 256>>>(f1, f2, tgt, (float*)d_out, out_size);
}